// round 14
// baseline (speedup 1.0000x reference)
#include <cuda_runtime.h>
#include <cuda_bf16.h>
#include <cstdint>

// ============================================================================
// output = 100/512 * (#pos edges with logit<=0.5 + #neg edges with logit>0.5)
// logit = W2 . relu(W1 . relu(x_i*x_j) + b1) + b2.
// (mean of segment sums == total/NUM_GRAPHS => `batch` irrelevant.)
//
// R14: W1 register-resident. N split across warps (2 row-groups x 5 warps,
// each warp owns 4 N-chunks = 32 cols; B-fragments live in 80 regs for the
// WHOLE kernel). Inner loop = 2 A-ldsm + 8 register-operand MMAs per k-step;
// zero B smem traffic (was the L1 ceiling: R12 L1=68.1% @ tensor=47.2%).
// Epilogue is separable over n -> per-warp partial logits, summed across the
// group via smem staging + one __syncthreads per 64-edge tile.
// ============================================================================

#define NUM_GRAPHS 512
#define HDIM 160
#define TILE_M 64
#define NTHREADS 320          // 10 warps: 2 groups x 5 warps
#define ROWB 336              // padded row pitch (bytes): conflict-free ldsm

// ---- device state (no cudaMalloc allowed) ----
__device__ __nv_bfloat16 g_xbf[16000000];   // 100000 x 160 bf16 = 32MB
__device__ int g_count = 0;
__device__ int g_done  = 0;

// ---- dynamic SMEM layout (bytes) ----
#define OFF_A0   0                          // 64 x 336 = 21504
#define OFF_A1   21504                      // 64 x 336 = 21504
#define OFF_B    43008                      // 160 x 336 = 53760 (init only)
#define OFF_BW   96768                      // float2[160] {b1,w2} = 1280
#define OFF_SACC 98048                      // 2 tb x 2 grp x 5 w x 32 x 4B = 2560
#define SMEM_TOTAL 100608

__device__ __forceinline__ uint32_t smem_u32(const void* p) {
    uint32_t a;
    asm("{ .reg .u64 t; cvta.to.shared.u64 t, %1; cvt.u32.u64 %0, t; }"
        : "=r"(a) : "l"(p));
    return a;
}

__device__ __forceinline__ void ldsm_x4(uint32_t* r, uint32_t addr) {
    asm volatile("ldmatrix.sync.aligned.m8n8.x4.shared.b16 {%0,%1,%2,%3}, [%4];"
                 : "=r"(r[0]), "=r"(r[1]), "=r"(r[2]), "=r"(r[3]) : "r"(addr));
}

__device__ __forceinline__ void mma16816(float* d, const uint32_t* a,
                                         const uint32_t* b) {
    asm volatile(
        "mma.sync.aligned.m16n8k16.row.col.f32.bf16.bf16.f32 "
        "{%0,%1,%2,%3}, {%4,%5,%6,%7}, {%8,%9}, {%0,%1,%2,%3};"
        : "+f"(d[0]), "+f"(d[1]), "+f"(d[2]), "+f"(d[3])
        : "r"(a[0]), "r"(a[1]), "r"(a[2]), "r"(a[3]), "r"(b[0]), "r"(b[1]));
}

// bf16x2 multiply + relu, packed
__device__ __forceinline__ uint32_t bfmr(uint32_t a, uint32_t b) {
    __nv_bfloat162 x = *reinterpret_cast<__nv_bfloat162*>(&a);
    __nv_bfloat162 y = *reinterpret_cast<__nv_bfloat162*>(&b);
    __nv_bfloat162 z = __hmul2(x, y);
    const __nv_bfloat162 zero = __float2bfloat162_rn(0.0f);
    z = __hmax2(z, zero);
    return *reinterpret_cast<uint32_t*>(&z);
}

// gather: warps 0..7 each own 8 edges of the next tile (rows wid*8..wid*8+7).
// lane quad q = lid>>2 -> edge q; it in [0,5): chunk = it*4 + (lid&3).
// Each quad reads 64B contiguous per side. Indices on lanes 0..7 (shfl).
#define GLOAD(it) do {                                            \
    int _eo = lid >> 2;                                           \
    int _ch = (it) * 4 + (lid & 3);                               \
    int _ii = __shfl_sync(0xFFFFFFFFu, myI, _eo);                 \
    int _jj = __shfl_sync(0xFFFFFFFFu, myJ, _eo);                 \
    va = xrows[(size_t)_ii * 20 + _ch];                           \
    vb = xrows[(size_t)_jj * 20 + _ch];                           \
} while (0)

#define GSTORE(it) do {                                           \
    int _row = wid * 8 + (lid >> 2);                              \
    int _ch  = (it) * 4 + (lid & 3);                              \
    uint4 _r;                                                     \
    _r.x = bfmr(va.x, vb.x);                                      \
    _r.y = bfmr(va.y, vb.y);                                      \
    _r.z = bfmr(va.z, vb.z);                                      \
    _r.w = bfmr(va.w, vb.w);                                      \
    *reinterpret_cast<uint4*>(smem + dstOff + _row * ROWB + _ch * 16) = _r; \
} while (0)

// ============================================================================
// Kernel 0: convert x -> bf16 scratch, zero counter
// ============================================================================
__global__ void cvt_kernel(const float* __restrict__ x, int n4) {
    if (blockIdx.x == 0 && threadIdx.x == 0) g_count = 0;
    int stride = gridDim.x * blockDim.x;
    uint2* out = reinterpret_cast<uint2*>(g_xbf);
    const float4* in = reinterpret_cast<const float4*>(x);
    for (int i = blockIdx.x * blockDim.x + threadIdx.x; i < n4; i += stride) {
        float4 v = in[i];
        __nv_bfloat162 p0 = __floats2bfloat162_rn(v.x, v.y);
        __nv_bfloat162 p1 = __floats2bfloat162_rn(v.z, v.w);
        uint2 o;
        o.x = *reinterpret_cast<uint32_t*>(&p0);
        o.y = *reinterpret_cast<uint32_t*>(&p1);
        out[i] = o;
    }
}

// ============================================================================
// Kernel 1: persistent fused edge-MLP + misclassification count + output
// ============================================================================
__global__ void __launch_bounds__(NTHREADS, 1)
gae_main_kernel(const int* __restrict__ pos, const int* __restrict__ neg,
                const float* __restrict__ W1, const float* __restrict__ b1,
                const float* __restrict__ W2, const float* __restrict__ b2,
                int Ep, int En, float* __restrict__ out) {
    extern __shared__ char smem[];
    const uint32_t sb = smem_u32(smem);
    const int tid = threadIdx.x;
    const int wid = tid >> 5;
    const int lid = tid & 31;
    const int Etot = Ep + En;
    const int ntiles = (Etot + TILE_M - 1) / TILE_M;

    const int grp    = (wid >= 5) ? 1 : 0;     // row-group (32 rows each)
    const int wlocal = wid - grp * 5;          // 0..4 within group
    const int jbase  = wlocal * 4;             // this warp's 4 N-chunks

    // --- load W1 -> SMEM B [160 rows x 336B pitch], f32 -> bf16 (init only) ---
    {
        const float4* w1v = reinterpret_cast<const float4*>(W1);
        for (int idx = tid; idx < 6400; idx += NTHREADS) {
            int n  = idx / 40;
            int kc = idx - n * 40;
            float4 w = w1v[idx];
            __nv_bfloat162 p0 = __floats2bfloat162_rn(w.x, w.y);
            __nv_bfloat162 p1 = __floats2bfloat162_rn(w.z, w.w);
            uint2 v;
            v.x = *reinterpret_cast<uint32_t*>(&p0);
            v.y = *reinterpret_cast<uint32_t*>(&p1);
            *reinterpret_cast<uint2*>(smem + OFF_B + n * ROWB + kc * 8) = v;
        }
    }
    if (tid < HDIM) {
        reinterpret_cast<float2*>(smem + OFF_BW)[tid] = make_float2(b1[tid], W2[tid]);
    }

    const float2* sbw = reinterpret_cast<const float2*>(smem + OFF_BW);
    const uint4* xrows = reinterpret_cast<const uint4*>(g_xbf);
    const float b2v = b2[0];

    int tile = blockIdx.x;

    // ---- prologue: gather first tile into buf0 (warps 0..7, 8 edges each) ----
    if (tile < ntiles && wid < 8) {
        int myI = 0, myJ = 0;
        if (lid < 8) {
            int g = tile * TILE_M + wid * 8 + lid;
            if (g < Etot) {
                if (g < Ep) { myI = pos[g];      myJ = pos[g + Ep]; }
                else        { int q = g - Ep; myI = neg[q]; myJ = neg[q + En]; }
            }
        }
        const uint32_t dstOff = OFF_A0;
        uint4 va, vb;
        #pragma unroll
        for (int it = 0; it < 5; ++it) { GLOAD(it); GSTORE(it); }
    }
    __syncthreads();   // B smem + BW + first A tile ready

    // ---- W1 fragments -> registers, PERMANENT (80 regs: 4 chunks x 20) ----
    uint32_t bres[4][20];
    {
        const uint32_t bBase = sb + OFF_B
            + (uint32_t)((lid & 7) * ROWB) + (uint32_t)((lid >> 3) * 16);
        #pragma unroll
        for (int jc = 0; jc < 4; ++jc) {
            const uint32_t bj = bBase + (uint32_t)((jbase + jc) * 8 * ROWB);
            #pragma unroll
            for (int t = 0; t < 5; ++t)
                ldsm_x4(&bres[jc][t * 4], bj + (uint32_t)(t * 64));
        }
    }

    int cnt = 0;
    int buf = 0, tb = 0;

    for (; tile < ntiles; tile += gridDim.x) {
        const int nt = tile + gridDim.x;
        const bool gat = (nt < ntiles) && (wid < 8);
        int myI = 0, myJ = 0;
        if (gat && lid < 8) {
            int g = nt * TILE_M + wid * 8 + lid;
            if (g < Etot) {
                if (g < Ep) { myI = pos[g];      myJ = pos[g + Ep]; }
                else        { int q = g - Ep; myI = neg[q]; myJ = neg[q + En]; }
            }
        }
        const uint32_t aB = sb + (buf ? OFF_A1 : OFF_A0)
            + (uint32_t)((grp * 32 + ((lid >> 3) & 1) * 8 + (lid & 7)) * ROWB
                         + (lid >> 4) * 16);
        const uint32_t dstOff = (buf ? OFF_A0 : OFF_A1);

        uint4 va, vb;
        if (gat) GLOAD(0);

        // 8 independent accumulator chains: dd[jc][m][4]
        float dd[4][2][4];
        #pragma unroll
        for (int jc = 0; jc < 4; ++jc)
            #pragma unroll
            for (int m = 0; m < 2; ++m)
                #pragma unroll
                for (int r = 0; r < 4; ++r) dd[jc][m][r] = 0.0f;

        // A fragments streamed per k-step (double-buffered, 16 regs)
        uint32_t afA[2][4], afB[2][4];
        ldsm_x4(afA[0], aB);
        ldsm_x4(afA[1], aB + (uint32_t)(16 * ROWB));

        #pragma unroll
        for (int s = 0; s < 10; ++s) {
            uint32_t (*cur)[4] = (s & 1) ? afB : afA;
            uint32_t (*nxt)[4] = (s & 1) ? afA : afB;
            if (s < 9) {
                ldsm_x4(nxt[0], aB + (uint32_t)((s + 1) * 32));
                ldsm_x4(nxt[1], aB + (uint32_t)(16 * ROWB + (s + 1) * 32));
            }
            const int bo = ((s >> 1) << 2) + ((s & 1) << 1);
            #pragma unroll
            for (int jc = 0; jc < 4; ++jc) {
                mma16816(dd[jc][0], cur[0], &bres[jc][bo]);
                mma16816(dd[jc][1], cur[1], &bres[jc][bo]);
            }
            if ((s & 1) && gat) {
                const int it = s >> 1;     // 0..4 at s=1,3,5,7,9
                GSTORE(it);
                if (it + 1 < 5) GLOAD(it + 1);
            }
        }

        // ---- partial epilogue over this warp's 32 cols ----
        float acc[2][2] = {{0.0f, 0.0f}, {0.0f, 0.0f}};
        #pragma unroll
        for (int jc = 0; jc < 4; ++jc) {
            const int n0 = (jbase + jc) * 8 + (lid & 3) * 2;
            const float2 bw0 = sbw[n0];
            const float2 bw1 = sbw[n0 + 1];
            #pragma unroll
            for (int m = 0; m < 2; ++m) {
                acc[m][0] += fmaxf(dd[jc][m][0] + bw0.x, 0.0f) * bw0.y
                           + fmaxf(dd[jc][m][1] + bw1.x, 0.0f) * bw1.y;
                acc[m][1] += fmaxf(dd[jc][m][2] + bw0.x, 0.0f) * bw0.y
                           + fmaxf(dd[jc][m][3] + bw1.x, 0.0f) * bw1.y;
            }
        }
        #pragma unroll
        for (int m = 0; m < 2; ++m)
            #pragma unroll
            for (int h = 0; h < 2; ++h) {
                acc[m][h] += __shfl_xor_sync(0xFFFFFFFFu, acc[m][h], 1);
                acc[m][h] += __shfl_xor_sync(0xFFFFFFFFu, acc[m][h], 2);
            }
        if ((lid & 3) == 0) {
            #pragma unroll
            for (int m = 0; m < 2; ++m)
                #pragma unroll
                for (int h = 0; h < 2; ++h) {
                    int rloc = m * 16 + h * 8 + (lid >> 2);
                    *reinterpret_cast<float*>(smem + OFF_SACC
                        + (((tb * 2 + grp) * 5 + wlocal) * 32 + rloc) * 4)
                        = acc[m][h];
                }
        }
        __syncthreads();   // partials staged; next-tile A fully written

        // ---- sum 5 partials per row, threshold, count (threads 0..63) ----
        if (tid < TILE_M) {
            int r = tile * TILE_M + tid;
            if (r < Etot) {
                int cg = tid >> 5, rl = tid & 31;
                float s = b2v;
                #pragma unroll
                for (int w = 0; w < 5; ++w)
                    s += *reinterpret_cast<const float*>(smem + OFF_SACC
                          + (((tb * 2 + cg) * 5 + w) * 32 + rl) * 4);
                bool pred = s > 0.5f;
                if (pred != (r < Ep)) cnt++;
            }
        }
        buf ^= 1;
        tb ^= 1;
    }

    // ---- reduce counts within warp, accumulate globally ----
    #pragma unroll
    for (int o = 16; o; o >>= 1) cnt += __shfl_xor_sync(0xFFFFFFFFu, cnt, o);
    if (lid == 0 && cnt) atomicAdd(&g_count, cnt);

    // ---- last CTA writes the scalar and resets state for the next call ----
    __syncthreads();
    if (tid == 0) {
        __threadfence();
        if (atomicAdd(&g_done, 1) == (int)gridDim.x - 1) {
            int total = atomicAdd(&g_count, 0);
            out[0] = (float)total * 0.1953125f;   // * 100 / 512, exact in f32
            g_count = 0;
            g_done  = 0;
        }
    }
}

// ============================================================================
extern "C" void kernel_launch(void* const* d_in, const int* in_sizes, int n_in,
                              void* d_out, int out_size) {
    const float* x   = (const float*)d_in[0];
    const int*   pos = (const int*)  d_in[1];
    const int*   neg = (const int*)  d_in[2];
    // d_in[3] = batch (irrelevant: mean of segment sums == total/512)
    const float* W1  = (const float*)d_in[4];
    const float* b1  = (const float*)d_in[5];
    const float* W2  = (const float*)d_in[6];
    const float* b2  = (const float*)d_in[7];

    int Ep = in_sizes[1] / 2;
    int En = in_sizes[2] / 2;
    int n4 = in_sizes[0] / 4;

    static int configured = 0;
    if (!configured) {
        cudaFuncSetAttribute(gae_main_kernel,
                             cudaFuncAttributeMaxDynamicSharedMemorySize,
                             SMEM_TOTAL);
        configured = 1;
    }

    int sms = 148;
    cudaDeviceGetAttribute(&sms, cudaDevAttrMultiProcessorCount, 0);
    if (sms <= 0) sms = 148;

    cvt_kernel<<<2048, 256>>>(x, n4);
    gae_main_kernel<<<sms, NTHREADS, SMEM_TOTAL>>>(pos, neg, W1, b1, W2, b2,
                                                   Ep, En, (float*)d_out);
}

// round 15
// speedup vs baseline: 1.0294x; 1.0294x over previous
#include <cuda_runtime.h>
#include <cuda_bf16.h>
#include <cstdint>

// ============================================================================
// output = 100/512 * (#pos edges with logit<=0.5 + #neg edges with logit>0.5)
// logit = W2 . relu(W1 . relu(x_i*x_j) + b1) + b2.
// (mean of segment sums == total/NUM_GRAPHS => `batch` irrelevant.)
//
// R15: 16-warp occupancy test with an honest 128-reg budget. m=1 per warp
// (16 rows, TILE_M=256) cuts af 80->40 regs so 512 threads fit without
// spills. Warp-private single-buffer A slices, no inter-tile CTA barriers,
// depth-2 gather pipeline, split-K accumulator chains (all proven in R11/12).
// Discriminates: legacy-mma latency-bound (gain ~25%) vs 512MAC/cyc cap (flat).
// ============================================================================

#define NUM_GRAPHS 512
#define HDIM 160
#define TILE_M 256
#define NTHREADS 512          // 16 warps, 16 rows each
#define ROWB 336              // padded row pitch (bytes): conflict-free ldsm

// ---- device state (no cudaMalloc allowed) ----
__device__ __nv_bfloat16 g_xbf[16000000];   // 100000 x 160 bf16 = 32MB
__device__ int g_count = 0;
__device__ int g_done  = 0;

// ---- dynamic SMEM layout (bytes) ----
#define OFF_A    0                          // 256 x 336 = 86016 (single buffer)
#define OFF_B    86016                      // 160 x 336 = 53760
#define OFF_BW   139776                     // float2[160] {b1,w2} = 1280
#define SMEM_TOTAL 141056

__device__ __forceinline__ uint32_t smem_u32(const void* p) {
    uint32_t a;
    asm("{ .reg .u64 t; cvta.to.shared.u64 t, %1; cvt.u32.u64 %0, t; }"
        : "=r"(a) : "l"(p));
    return a;
}

__device__ __forceinline__ void ldsm_x4(uint32_t* r, uint32_t addr) {
    asm volatile("ldmatrix.sync.aligned.m8n8.x4.shared.b16 {%0,%1,%2,%3}, [%4];"
                 : "=r"(r[0]), "=r"(r[1]), "=r"(r[2]), "=r"(r[3]) : "r"(addr));
}

__device__ __forceinline__ void mma16816(float* d, const uint32_t* a,
                                         const uint32_t* b) {
    asm volatile(
        "mma.sync.aligned.m16n8k16.row.col.f32.bf16.bf16.f32 "
        "{%0,%1,%2,%3}, {%4,%5,%6,%7}, {%8,%9}, {%0,%1,%2,%3};"
        : "+f"(d[0]), "+f"(d[1]), "+f"(d[2]), "+f"(d[3])
        : "r"(a[0]), "r"(a[1]), "r"(a[2]), "r"(a[3]), "r"(b[0]), "r"(b[1]));
}

// bf16x2 multiply + relu, packed
__device__ __forceinline__ uint32_t bfmr(uint32_t a, uint32_t b) {
    __nv_bfloat162 x = *reinterpret_cast<__nv_bfloat162*>(&a);
    __nv_bfloat162 y = *reinterpret_cast<__nv_bfloat162*>(&b);
    __nv_bfloat162 z = __hmul2(x, y);
    const __nv_bfloat162 zero = __float2bfloat162_rn(0.0f);
    z = __hmax2(z, zero);
    return *reinterpret_cast<uint32_t*>(&z);
}

// gather: each warp owns 16 edges (its 16 A rows). it in [0,10):
// eo = (lid>>2) + (it>=5 ? 8 : 0), ch = (it%5)*4 + (lid&3).
// Lane quads read 64B contiguous per side; indices live on lanes 0..15.
#define G_EO(it) ((lid >> 2) + (((it) >= 5) ? 8 : 0))
#define G_CH(it) (((it) % 5) * 4 + (lid & 3))

#define GLOAD(it, VA, VB) do {                                   \
    int _eo = G_EO(it);                                          \
    int _ch = G_CH(it);                                          \
    int _ii = __shfl_sync(0xFFFFFFFFu, myI, _eo);                \
    int _jj = __shfl_sync(0xFFFFFFFFu, myJ, _eo);                \
    VA = xrows[(size_t)_ii * 20 + _ch];                          \
    VB = xrows[(size_t)_jj * 20 + _ch];                          \
} while (0)

#define GSTORE(it, VA, VB) do {                                  \
    int _eo = G_EO(it);                                          \
    int _ch = G_CH(it);                                          \
    uint4 _r;                                                    \
    _r.x = bfmr((VA).x, (VB).x);                                 \
    _r.y = bfmr((VA).y, (VB).y);                                 \
    _r.z = bfmr((VA).z, (VB).z);                                 \
    _r.w = bfmr((VA).w, (VB).w);                                 \
    *reinterpret_cast<uint4*>(smem + dstOff + _eo * ROWB + _ch * 16) = _r; \
} while (0)

// load the 20 B-fragment regs for column-chunk j (5x ldsm.x4)
__device__ __forceinline__ void load_b20(uint32_t* br, uint32_t bBase, int j) {
    const uint32_t bj = bBase + (uint32_t)(j * 8 * ROWB);
    #pragma unroll
    for (int t = 0; t < 5; ++t) ldsm_x4(br + 4 * t, bj + (uint32_t)(t * 64));
}

// 10 MMAs into 2 independent accumulator chains (k-parity split)
__device__ __forceinline__ void mma10(float dd[2][4],
                                      const uint32_t af[10][4],
                                      const uint32_t* br) {
    #pragma unroll
    for (int s = 0; s < 10; ++s) {
        const uint32_t* b = br + ((s >> 1) << 2) + ((s & 1) << 1);
        mma16816(dd[s & 1], af[s], b);
    }
}

// ============================================================================
// Kernel 0: convert x -> bf16 scratch, zero counter
// ============================================================================
__global__ void cvt_kernel(const float* __restrict__ x, int n4) {
    if (blockIdx.x == 0 && threadIdx.x == 0) g_count = 0;
    int stride = gridDim.x * blockDim.x;
    uint2* out = reinterpret_cast<uint2*>(g_xbf);
    const float4* in = reinterpret_cast<const float4*>(x);
    for (int i = blockIdx.x * blockDim.x + threadIdx.x; i < n4; i += stride) {
        float4 v = in[i];
        __nv_bfloat162 p0 = __floats2bfloat162_rn(v.x, v.y);
        __nv_bfloat162 p1 = __floats2bfloat162_rn(v.z, v.w);
        uint2 o;
        o.x = *reinterpret_cast<uint32_t*>(&p0);
        o.y = *reinterpret_cast<uint32_t*>(&p1);
        out[i] = o;
    }
}

// ============================================================================
// Kernel 1: persistent fused edge-MLP + misclassification count + output
// ============================================================================
__global__ void __launch_bounds__(NTHREADS, 1)
gae_main_kernel(const int* __restrict__ pos, const int* __restrict__ neg,
                const float* __restrict__ W1, const float* __restrict__ b1,
                const float* __restrict__ W2, const float* __restrict__ b2,
                int Ep, int En, float* __restrict__ out) {
    extern __shared__ char smem[];
    const uint32_t sb = smem_u32(smem);
    const int tid = threadIdx.x;
    const int wid = tid >> 5;
    const int lid = tid & 31;
    const int Etot = Ep + En;
    const int ntiles = (Etot + TILE_M - 1) / TILE_M;

    // --- load W1 -> SMEM B [160 rows x 336B pitch], f32 -> bf16 ---
    {
        const float4* w1v = reinterpret_cast<const float4*>(W1);
        for (int idx = tid; idx < 6400; idx += NTHREADS) {
            int n  = idx / 40;
            int kc = idx - n * 40;
            float4 w = w1v[idx];
            __nv_bfloat162 p0 = __floats2bfloat162_rn(w.x, w.y);
            __nv_bfloat162 p1 = __floats2bfloat162_rn(w.z, w.w);
            uint2 v;
            v.x = *reinterpret_cast<uint32_t*>(&p0);
            v.y = *reinterpret_cast<uint32_t*>(&p1);
            *reinterpret_cast<uint2*>(smem + OFF_B + n * ROWB + kc * 8) = v;
        }
    }
    if (tid < HDIM) {
        reinterpret_cast<float2*>(smem + OFF_BW)[tid] = make_float2(b1[tid], W2[tid]);
    }

    const float2* sbw = reinterpret_cast<const float2*>(smem + OFF_BW);
    const uint4* xrows = reinterpret_cast<const uint4*>(g_xbf);  // 20 uint4/row
    const float b2v = b2[0];

    // per-thread ldmatrix address components (warp-private 16-row A slice)
    const uint32_t aBase = sb + OFF_A
        + (uint32_t)((wid * 16 + ((lid >> 3) & 1) * 8 + (lid & 7)) * ROWB
                     + (lid >> 4) * 16);
    const uint32_t dstOff = OFF_A + (uint32_t)(wid * 16 * ROWB);
    const uint32_t bBase = sb + OFF_B
        + (uint32_t)((lid & 7) * ROWB) + (uint32_t)((lid >> 3) * 16);

    int cnt = 0;
    int tile = blockIdx.x;

    __syncthreads();                           // W1/BW ready (only CTA barrier)

    if (tile < ntiles) {
        // ---- prologue: gather this warp's 16-edge slice of the first tile ----
        {
            int myI = 0, myJ = 0;
            if (lid < 16) {
                int g = tile * TILE_M + wid * 16 + lid;
                if (g < Etot) {
                    if (g < Ep) { myI = pos[g];      myJ = pos[g + Ep]; }
                    else        { int q = g - Ep; myI = neg[q]; myJ = neg[q + En]; }
                }
            }
            #pragma unroll
            for (int it = 0; it < 10; ++it) {
                uint4 va, vb;
                GLOAD(it, va, vb);
                GSTORE(it, va, vb);
            }
        }
        __syncwarp();   // order STS before ldsm (warp-private slice)

        for (; tile < ntiles; tile += gridDim.x) {
            // ---- next-tile edge indices (register-resident, per warp) ----
            const int nt = tile + gridDim.x;
            const bool gat = (nt < ntiles);
            int myI = 0, myJ = 0;
            if (gat && lid < 16) {
                int g = nt * TILE_M + wid * 16 + lid;
                if (g < Etot) {
                    if (g < Ep) { myI = pos[g];      myJ = pos[g + Ep]; }
                    else        { int q = g - Ep; myI = neg[q]; myJ = neg[q + En]; }
                }
            }

            // ---- A fragments: this warp's 16 rows, all K (40 regs).
            // All af ldsm results consumed before the first next-tile GSTORE
            // issues (LSU program order) -> single-buffered slice is safe. ----
            uint32_t af[10][4];
            #pragma unroll
            for (int s = 0; s < 10; ++s)
                ldsm_x4(af[s], aBase + (uint32_t)(s * 32));

            // ---- depth-2 gather pipeline prefetch ----
            uint4 va[2], vb[2];
            if (gat) { GLOAD(0, va[0], vb[0]); GLOAD(1, va[1], vb[1]); }

            float acc[2] = {0.0f, 0.0f};
            uint32_t br[20];

            // ---- j-loop: 20 column-chunks, gather step every other j ----
            #pragma unroll 2
            for (int j = 0; j < 20; ++j) {
                load_b20(br, bBase, j);
                float dd[2][4] = {{0.f,0.f,0.f,0.f},{0.f,0.f,0.f,0.f}};
                mma10(dd, af, br);
                if (gat && (j & 1)) {
                    const int it = j >> 1;          // 0..9
                    GSTORE(it, va[it & 1], vb[it & 1]);
                    if (it + 2 < 10) GLOAD(it + 2, va[it & 1], vb[it & 1]);
                }
                const int n0 = j * 8 + (lid & 3) * 2;
                const float2 bw0 = sbw[n0];
                const float2 bw1 = sbw[n0 + 1];
                acc[0] += fmaxf(dd[0][0] + dd[1][0] + bw0.x, 0.0f) * bw0.y
                        + fmaxf(dd[0][1] + dd[1][1] + bw1.x, 0.0f) * bw1.y;
                acc[1] += fmaxf(dd[0][2] + dd[1][2] + bw0.x, 0.0f) * bw0.y
                        + fmaxf(dd[0][3] + dd[1][3] + bw1.x, 0.0f) * bw1.y;
            }

            // ---- reduce 4 lanes/row, threshold, count ----
            #pragma unroll
            for (int h = 0; h < 2; ++h) {
                float a = acc[h];
                a += __shfl_xor_sync(0xFFFFFFFFu, a, 1);
                a += __shfl_xor_sync(0xFFFFFFFFu, a, 2);
                if ((lid & 3) == 0) {
                    int r = tile * TILE_M + wid * 16 + (lid >> 2) + h * 8;
                    if (r < Etot) {
                        bool pred = (a + b2v) > 0.5f;
                        if (pred != (r < Ep)) cnt++;
                    }
                }
            }
            __syncwarp();   // order this warp's GSTOREs before next ldsm af
        }
    }

    // ---- reduce counts within warp, accumulate globally ----
    #pragma unroll
    for (int o = 16; o; o >>= 1) cnt += __shfl_xor_sync(0xFFFFFFFFu, cnt, o);
    if (lid == 0 && cnt) atomicAdd(&g_count, cnt);

    // ---- last CTA writes the scalar and resets state for the next call ----
    __syncthreads();
    if (tid == 0) {
        __threadfence();
        if (atomicAdd(&g_done, 1) == (int)gridDim.x - 1) {
            int total = atomicAdd(&g_count, 0);
            out[0] = (float)total * 0.1953125f;   // * 100 / 512, exact in f32
            g_count = 0;
            g_done  = 0;
        }
    }
}

// ============================================================================
extern "C" void kernel_launch(void* const* d_in, const int* in_sizes, int n_in,
                              void* d_out, int out_size) {
    const float* x   = (const float*)d_in[0];
    const int*   pos = (const int*)  d_in[1];
    const int*   neg = (const int*)  d_in[2];
    // d_in[3] = batch (irrelevant: mean of segment sums == total/512)
    const float* W1  = (const float*)d_in[4];
    const float* b1  = (const float*)d_in[5];
    const float* W2  = (const float*)d_in[6];
    const float* b2  = (const float*)d_in[7];

    int Ep = in_sizes[1] / 2;
    int En = in_sizes[2] / 2;
    int n4 = in_sizes[0] / 4;

    static int configured = 0;
    if (!configured) {
        cudaFuncSetAttribute(gae_main_kernel,
                             cudaFuncAttributeMaxDynamicSharedMemorySize,
                             SMEM_TOTAL);
        configured = 1;
    }

    int sms = 148;
    cudaDeviceGetAttribute(&sms, cudaDevAttrMultiProcessorCount, 0);
    if (sms <= 0) sms = 148;

    cvt_kernel<<<2048, 256>>>(x, n4);
    gae_main_kernel<<<sms, NTHREADS, SMEM_TOTAL>>>(pos, neg, W1, b1, W2, b2,
                                                   Ep, En, (float*)d_out);
}